// round 4
// baseline (speedup 1.0000x reference)
#include <cuda_runtime.h>
#include <math.h>

#define N_CELLS 20
#define IN 8
#define HID 10
#define NGATES 800
#define FEAT 200
#define H1 50
#define H2 10

// Dynamic shared layout (float offsets)
#define OFF_WIHT  0                       // 6400  transposed [i][row]
#define OFF_WHHT  (OFF_WIHT + 6400)       // 8000  transposed [j][row]
#define OFF_W1    (OFF_WHHT + 8000)       // 10000
#define OFF_GATES (OFF_W1 + 10000)        // 800
#define OFF_FEAT  (OFF_GATES + 800)       // 200
#define OFF_H0    (OFF_FEAT + 200)        // 200
#define OFF_C0    (OFF_H0 + 200)          // 200
#define OFF_X     (OFF_C0 + 200)          // 8
#define OFF_B1    (OFF_X + 8)             // 50
#define OFF_W2    (OFF_B1 + 50)           // 500
#define OFF_B2    (OFF_W2 + 500)          // 10
#define OFF_W3    (OFF_B2 + 10)           // 10
#define OFF_H1    (OFF_W3 + 10)           // 50
#define OFF_H2    (OFF_H1 + 50)           // 10
#define OFF_B3    (OFF_H2 + 10)           // 1
#define SMEM_FLOATS (OFF_B3 + 1)
#define SMEM_BYTES  (SMEM_FLOATS * 4)

__device__ __forceinline__ float tanh_fast(float x) {
    float xc = fminf(fmaxf(x, -15.0f), 15.0f);
    float e = __expf(2.0f * xc);
    return __fdividef(e - 1.0f, e + 1.0f);
}
__device__ __forceinline__ float sigmoid_fast(float x) {
    float xc = fminf(fmaxf(x, -30.0f), 30.0f);
    return __fdividef(1.0f, 1.0f + __expf(-xc));
}

__global__ __launch_bounds__(800, 1)
void lstm_mlp_fused(const float* __restrict__ x,
                    const float* __restrict__ h0,
                    const float* __restrict__ c0,
                    const float* __restrict__ W_ih,
                    const float* __restrict__ W_hh,
                    const float* __restrict__ b_ih,
                    const float* __restrict__ b_hh,
                    const float* __restrict__ W1,
                    const float* __restrict__ b1,
                    const float* __restrict__ W2,
                    const float* __restrict__ b2,
                    const float* __restrict__ W3,
                    const float* __restrict__ b3,
                    float* __restrict__ out)
{
    extern __shared__ float sm[];
    const int t = threadIdx.x;

    // ======== Entry: all global traffic, scalar + coalesced ========
    float bias = b_ih[t] + b_hh[t];

    // W_ih -> transposed shared [i*800 + row] (coalesced reads)
    #pragma unroll
    for (int k = 0; k < 8; ++k) {
        int g = t + 800 * k;              // g < 6400
        float v = W_ih[g];
        sm[OFF_WIHT + (g & 7) * 800 + (g >> 3)] = v;
    }
    // W_hh -> transposed shared [j*800 + row]
    #pragma unroll
    for (int k = 0; k < 10; ++k) {
        int g = t + 800 * k;              // g < 8000
        float v = W_hh[g];
        sm[OFF_WHHT + (g % HID) * 800 + (g / HID)] = v;
    }
    // W1 -> straight copy
    for (int g = t; g < 10000; g += 800)
        sm[OFF_W1 + g] = W1[g];
    // Small arrays (disjoint thread ranges, coalesced scalar)
    if (t < 200) {
        sm[OFF_H0 + t] = h0[t];
    } else if (t < 400) {
        sm[OFF_C0 + (t - 200)] = c0[t - 200];
    } else if (t < 656) {
        int g = t - 400;
        sm[OFF_W2 + g] = W2[g];
        g += 256;
        if (g < 500) sm[OFF_W2 + g] = W2[g];
    } else if (t < 706) {
        sm[OFF_B1 + (t - 656)] = b1[t - 656];
    } else if (t < 716) {
        sm[OFF_B2 + (t - 706)] = b2[t - 706];
    } else if (t < 726) {
        sm[OFF_W3 + (t - 716)] = W3[t - 716];
    } else if (t < 734) {
        sm[OFF_X + (t - 726)] = x[t - 726];
    } else if (t == 734) {
        sm[OFF_B3] = b3[0];
    }
    __syncthreads();

    // ======== Stage 1: gates (thread t = gate row t), all conflict-free LDS ====
    {
        const int cell = t / 40;
        float acc = bias;
        #pragma unroll
        for (int i = 0; i < IN; ++i)
            acc = fmaf(sm[OFF_WIHT + i * 800 + t], sm[OFF_X + i], acc);
        #pragma unroll
        for (int j = 0; j < HID; ++j)
            acc = fmaf(sm[OFF_WHHT + j * 800 + t], sm[OFF_H0 + cell * HID + j], acc);
        sm[OFF_GATES + t] = acc;
    }
    __syncthreads();

    // ======== Stage 2: LSTM pointwise + feature reorder (gen bank first) ======
    if (t < FEAT) {
        const int cell = t / HID;
        const int j = t % HID;
        const float* g = sm + OFF_GATES + cell * 40 + j;
        float ig = sigmoid_fast(g[0]);
        float fg = sigmoid_fast(g[10]);
        float gg = tanh_fast(g[20]);
        float og = sigmoid_fast(g[30]);
        float c = fmaf(fg, sm[OFF_C0 + t], ig * gg);
        float h = og * tanh_fast(c);
        int fidx = (cell >= 10) ? (t - 100) : (100 + t);
        sm[OFF_FEAT + fidx] = h;
    }
    __syncthreads();

    // ======== Stage 3: h1 = tanh(W1 @ feat + b1): 16 lanes/row, 50*16=800 =====
    {
        const int row = t >> 4;           // 0..49
        const int lane = t & 15;
        const float* w = sm + OFF_W1 + row * FEAT;
        const float* f = sm + OFF_FEAT;
        float sum = 0.0f;
        #pragma unroll
        for (int u = 0; u < 12; ++u) {
            int idx = lane + (u << 4);
            sum = fmaf(w[idx], f[idx], sum);
        }
        if (lane < 8) {                   // tail 192..199
            int idx = 192 + lane;
            sum = fmaf(w[idx], f[idx], sum);
        }
        sum += __shfl_xor_sync(0xffffffffu, sum, 8);
        sum += __shfl_xor_sync(0xffffffffu, sum, 4);
        sum += __shfl_xor_sync(0xffffffffu, sum, 2);
        sum += __shfl_xor_sync(0xffffffffu, sum, 1);
        if (lane == 0) sm[OFF_H1 + row] = tanh_fast(sum + sm[OFF_B1 + row]);
    }
    __syncthreads();

    // ======== Stage 4: h2 = tanh(W2 @ h1 + b2): one warp per row ==============
    if (t < H2 * 32) {
        const int row = t >> 5;
        const int lane = t & 31;
        const float* w = sm + OFF_W2 + row * H1;
        float sum = w[lane] * sm[OFF_H1 + lane];
        if (lane < H1 - 32) sum = fmaf(w[32 + lane], sm[OFF_H1 + 32 + lane], sum);
        #pragma unroll
        for (int m = 16; m > 0; m >>= 1)
            sum += __shfl_xor_sync(0xffffffffu, sum, m);
        if (lane == 0) sm[OFF_H2 + row] = tanh_fast(sum + sm[OFF_B2 + row]);
    }
    __syncthreads();

    // ======== Stage 5: out = tanh(W3 @ h2 + b3): single warp ==================
    if (t < 32) {
        float sum = (t < H2) ? sm[OFF_W3 + t] * sm[OFF_H2 + t] : 0.0f;
        #pragma unroll
        for (int m = 16; m > 0; m >>= 1)
            sum += __shfl_xor_sync(0xffffffffu, sum, m);
        if (t == 0) out[0] = tanh_fast(sum + sm[OFF_B3]);
    }
}

extern "C" void kernel_launch(void* const* d_in, const int* in_sizes, int n_in,
                              void* d_out, int out_size) {
    (void)in_sizes; (void)n_in; (void)out_size;
    const float* x    = (const float*)d_in[0];
    const float* h0   = (const float*)d_in[1];
    const float* c0   = (const float*)d_in[2];
    const float* W_ih = (const float*)d_in[3];
    const float* W_hh = (const float*)d_in[4];
    const float* b_ih = (const float*)d_in[5];
    const float* b_hh = (const float*)d_in[6];
    const float* W1   = (const float*)d_in[7];
    const float* b1   = (const float*)d_in[8];
    const float* W2   = (const float*)d_in[9];
    const float* b2   = (const float*)d_in[10];
    const float* W3   = (const float*)d_in[11];
    const float* b3   = (const float*)d_in[12];
    float* out = (float*)d_out;

    static bool attr_set = false;
    if (!attr_set) {
        cudaFuncSetAttribute(lstm_mlp_fused,
                             cudaFuncAttributeMaxDynamicSharedMemorySize,
                             SMEM_BYTES);
        attr_set = true;
    }

    lstm_mlp_fused<<<1, 800, SMEM_BYTES>>>(x, h0, c0, W_ih, W_hh, b_ih, b_hh,
                                           W1, b1, W2, b2, W3, b3, out);
}

// round 5
// speedup vs baseline: 1.4250x; 1.4250x over previous
#include <cuda_runtime.h>
#include <math.h>

#define N_CELLS 20
#define IN 8
#define HID 10
#define NGATES 800
#define FEAT 200
#define H1 50
#define H2 10

__device__ __forceinline__ float tanh_fast(float x) {
    float xc = fminf(fmaxf(x, -15.0f), 15.0f);
    float e = __expf(2.0f * xc);
    return __fdividef(e - 1.0f, e + 1.0f);
}
__device__ __forceinline__ float sigmoid_fast(float x) {
    float xc = fminf(fmaxf(x, -30.0f), 30.0f);
    return __fdividef(1.0f, 1.0f + __expf(-xc));
}

__global__ __launch_bounds__(800, 1)
void lstm_mlp_fused(const float* __restrict__ x,
                    const float* __restrict__ h0,
                    const float* __restrict__ c0,
                    const float* __restrict__ W_ih,
                    const float* __restrict__ W_hh,
                    const float* __restrict__ b_ih,
                    const float* __restrict__ b_hh,
                    const float* __restrict__ W1,
                    const float* __restrict__ b1,
                    const float* __restrict__ W2,
                    const float* __restrict__ b2,
                    const float* __restrict__ W3,
                    const float* __restrict__ b3,
                    float* __restrict__ out)
{
    __shared__ float s_x[IN];
    __shared__ float s_h0[FEAT];
    __shared__ float s_gates[NGATES];
    __shared__ float s_feat[FEAT];
    __shared__ float s_h1[H1];
    __shared__ float s_h2[H2];

    const int t = threadIdx.x;
    const int lane16 = t & 15;
    const int row16  = t >> 4;        // stage-3 row: 0..49

    // ================= Entry: issue ALL global loads, front-batched ==========
    // Stage-1 operands (per-thread gate row t)
    float wih0 = W_ih[t * IN + 0], wih1 = W_ih[t * IN + 1];
    float wih2 = W_ih[t * IN + 2], wih3 = W_ih[t * IN + 3];
    float wih4 = W_ih[t * IN + 4], wih5 = W_ih[t * IN + 5];
    float wih6 = W_ih[t * IN + 6], wih7 = W_ih[t * IN + 7];
    float whh0 = W_hh[t * HID + 0], whh1 = W_hh[t * HID + 1];
    float whh2 = W_hh[t * HID + 2], whh3 = W_hh[t * HID + 3];
    float whh4 = W_hh[t * HID + 4], whh5 = W_hh[t * HID + 5];
    float whh6 = W_hh[t * HID + 6], whh7 = W_hh[t * HID + 7];
    float whh8 = W_hh[t * HID + 8], whh9 = W_hh[t * HID + 9];
    float bias = b_ih[t] + b_hh[t];

    // Stage-3 operands: W1 row slice, 16 lanes per row (12 full + 1 tail)
    const float* w1p = W1 + row16 * FEAT + lane16;
    float w1r[12];
    #pragma unroll
    for (int u = 0; u < 12; ++u) w1r[u] = w1p[u << 4];
    float w1t = (lane16 < 8) ? w1p[192 - lane16 + lane16] : 0.0f; // W1[row*200+192+lane]
    // (idx arithmetic: w1p already includes +lane16, so offset is 192)
    float b1r = (lane16 == 0) ? b1[row16] : 0.0f;

    // Stage-2 operand
    float c0r = (t < FEAT) ? c0[t] : 0.0f;

    // Stage-4 operands (threads 0..319: row = t>>5, lane = t&31)
    float w2a = 0.0f, w2b = 0.0f, b2r = 0.0f;
    if (t < H2 * 32) {
        const int r4 = t >> 5, l4 = t & 31;
        w2a = W2[r4 * H1 + l4];
        if (l4 < H1 - 32) w2b = W2[r4 * H1 + 32 + l4];
        if (l4 == 0) b2r = b2[r4];
    }
    // Stage-5 operands
    float w3r = (t < H2) ? W3[t] : 0.0f;
    float b3r = (t == 0) ? b3[0] : 0.0f;

    // Tiny shared vectors
    if (t < IN)   s_x[t]  = x[t];
    if (t < FEAT) s_h0[t] = h0[t];
    __syncthreads();

    // ================= Stage 1: gates = W_ih·x + W_hh·h0 + b =================
    {
        const float* hr = s_h0 + (t / 40) * HID;
        float acc = bias;
        acc = fmaf(wih0, s_x[0], acc);  acc = fmaf(wih1, s_x[1], acc);
        acc = fmaf(wih2, s_x[2], acc);  acc = fmaf(wih3, s_x[3], acc);
        acc = fmaf(wih4, s_x[4], acc);  acc = fmaf(wih5, s_x[5], acc);
        acc = fmaf(wih6, s_x[6], acc);  acc = fmaf(wih7, s_x[7], acc);
        acc = fmaf(whh0, hr[0], acc);   acc = fmaf(whh1, hr[1], acc);
        acc = fmaf(whh2, hr[2], acc);   acc = fmaf(whh3, hr[3], acc);
        acc = fmaf(whh4, hr[4], acc);   acc = fmaf(whh5, hr[5], acc);
        acc = fmaf(whh6, hr[6], acc);   acc = fmaf(whh7, hr[7], acc);
        acc = fmaf(whh8, hr[8], acc);   acc = fmaf(whh9, hr[9], acc);
        s_gates[t] = acc;
    }
    __syncthreads();

    // ================= Stage 2: LSTM pointwise + feature reorder ==============
    if (t < FEAT) {
        const int cell = t / HID;
        const float* g = s_gates + cell * 40 + (t % HID);
        float ig = sigmoid_fast(g[0]);
        float fg = sigmoid_fast(g[10]);
        float gg = tanh_fast(g[20]);
        float og = sigmoid_fast(g[30]);
        float c = fmaf(fg, c0r, ig * gg);
        float h = og * tanh_fast(c);
        int fidx = (cell >= 10) ? (t - 100) : (100 + t);   // gen bank first
        s_feat[fidx] = h;
    }
    __syncthreads();

    // ================= Stage 3: h1 = tanh(W1 @ feat + b1), 16 lanes/row ======
    {
        float sum = 0.0f;
        #pragma unroll
        for (int u = 0; u < 12; ++u)
            sum = fmaf(w1r[u], s_feat[lane16 + (u << 4)], sum);
        if (lane16 < 8)
            sum = fmaf(w1t, s_feat[192 + lane16], sum);
        sum += __shfl_xor_sync(0xffffffffu, sum, 8);
        sum += __shfl_xor_sync(0xffffffffu, sum, 4);
        sum += __shfl_xor_sync(0xffffffffu, sum, 2);
        sum += __shfl_xor_sync(0xffffffffu, sum, 1);
        if (lane16 == 0) s_h1[row16] = tanh_fast(sum + b1r);
    }
    __syncthreads();

    // ================= Stage 4: h2 = tanh(W2 @ h1 + b2), 1 warp/row ==========
    if (t < H2 * 32) {
        const int l4 = t & 31;
        float sum = w2a * s_h1[l4];
        if (l4 < H1 - 32) sum = fmaf(w2b, s_h1[32 + l4], sum);
        #pragma unroll
        for (int m = 16; m > 0; m >>= 1)
            sum += __shfl_xor_sync(0xffffffffu, sum, m);
        if (l4 == 0) s_h2[t >> 5] = tanh_fast(sum + b2r);
    }
    __syncthreads();

    // ================= Stage 5: out = tanh(W3 @ h2 + b3), 1 warp =============
    if (t < 32) {
        float sum = (t < H2) ? w3r * s_h2[t] : 0.0f;
        #pragma unroll
        for (int m = 16; m > 0; m >>= 1)
            sum += __shfl_xor_sync(0xffffffffu, sum, m);
        if (t == 0) out[0] = tanh_fast(sum + b3r);
    }
}

extern "C" void kernel_launch(void* const* d_in, const int* in_sizes, int n_in,
                              void* d_out, int out_size) {
    (void)in_sizes; (void)n_in; (void)out_size;
    const float* x    = (const float*)d_in[0];
    const float* h0   = (const float*)d_in[1];
    const float* c0   = (const float*)d_in[2];
    const float* W_ih = (const float*)d_in[3];
    const float* W_hh = (const float*)d_in[4];
    const float* b_ih = (const float*)d_in[5];
    const float* b_hh = (const float*)d_in[6];
    const float* W1   = (const float*)d_in[7];
    const float* b1   = (const float*)d_in[8];
    const float* W2   = (const float*)d_in[9];
    const float* b2   = (const float*)d_in[10];
    const float* W3   = (const float*)d_in[11];
    const float* b3   = (const float*)d_in[12];
    float* out = (float*)d_out;

    lstm_mlp_fused<<<1, 800>>>(x, h0, c0, W_ih, W_hh, b_ih, b_hh,
                               W1, b1, W2, b2, W3, b3, out);
}

// round 6
// speedup vs baseline: 1.4723x; 1.0332x over previous
#include <cuda_runtime.h>
#include <math.h>

#define N_CELLS 20
#define IN 8
#define HID 10
#define NGATES 800
#define FEAT 200
#define H1 50
#define H2 10

#define PITCH_IH 9     // odd pitch: stage-1 LDS stride 9, coprime to 32
#define PITCH_HH 11    // odd pitch: stage-1 LDS stride 11, coprime to 32

// Dynamic shared layout (float offsets)
#define OFF_WIH   0
#define OFF_WHH   (OFF_WIH + NGATES * PITCH_IH)    // 7200
#define OFF_X     (OFF_WHH + NGATES * PITCH_HH)    // 16000
#define OFF_H0    (OFF_X + IN)                     // 16008
#define OFF_GATES (OFF_H0 + FEAT)                  // 16208
#define OFF_FEAT  (OFF_GATES + NGATES)             // 17008
#define OFF_H1    (OFF_FEAT + FEAT)                // 17208
#define OFF_H2    (OFF_H1 + H1)                    // 17258
#define SMEM_FLOATS (OFF_H2 + H2)                  // 17268
#define SMEM_BYTES  (SMEM_FLOATS * 4)              // 69072

__device__ __forceinline__ float tanh_fast(float x) {
    float xc = fminf(fmaxf(x, -15.0f), 15.0f);
    float e = __expf(2.0f * xc);
    return __fdividef(e - 1.0f, e + 1.0f);
}
__device__ __forceinline__ float sigmoid_fast(float x) {
    float xc = fminf(fmaxf(x, -30.0f), 30.0f);
    return __fdividef(1.0f, 1.0f + __expf(-xc));
}

__global__ __launch_bounds__(800, 1)
void lstm_mlp_fused(const float* __restrict__ x,
                    const float* __restrict__ h0,
                    const float* __restrict__ c0,
                    const float* __restrict__ W_ih,
                    const float* __restrict__ W_hh,
                    const float* __restrict__ b_ih,
                    const float* __restrict__ b_hh,
                    const float* __restrict__ W1,
                    const float* __restrict__ b1,
                    const float* __restrict__ W2,
                    const float* __restrict__ b2,
                    const float* __restrict__ W3,
                    const float* __restrict__ b3,
                    float* __restrict__ out)
{
    extern __shared__ float sm[];
    const int t = threadIdx.x;
    const int lane16 = t & 15;
    const int row16  = t >> 4;        // stage-3 row 0..49

    // ================= Entry: coalesced global -> shared / registers =========
    float bias = b_ih[t] + b_hh[t];

    // W_ih: coalesced LDG, store padded row-major (<=2-way STS, CF LDS later)
    #pragma unroll
    for (int k = 0; k < 8; ++k) {
        int g = t + 800 * k;                         // g < 6400
        sm[OFF_WIH + (g >> 3) * PITCH_IH + (g & 7)] = W_ih[g];
    }
    // W_hh: coalesced LDG, padded row-major
    #pragma unroll
    for (int k = 0; k < 10; ++k) {
        int g = t + 800 * k;                         // g < 8000
        sm[OFF_WHH + (g / HID) * PITCH_HH + (g % HID)] = W_hh[g];
    }

    // Stage-3 operands: W1 row slice in registers, 16 lanes per row
    const float* w1p = W1 + row16 * FEAT + lane16;
    float w1r[12];
    #pragma unroll
    for (int u = 0; u < 12; ++u) w1r[u] = w1p[u << 4];
    float w1t = (lane16 < 8) ? w1p[192] : 0.0f;      // W1[row*200+192+lane]
    float b1r = (lane16 == 0) ? b1[row16] : 0.0f;

    // Stage-2 operand
    float c0r = (t < FEAT) ? c0[t] : 0.0f;

    // Stage-4 operands (threads 0..319)
    float w2a = 0.0f, w2b = 0.0f, b2r = 0.0f;
    if (t < H2 * 32) {
        const int r4 = t >> 5, l4 = t & 31;
        w2a = W2[r4 * H1 + l4];
        if (l4 < H1 - 32) w2b = W2[r4 * H1 + 32 + l4];
        if (l4 == 0) b2r = b2[r4];
    }
    // Stage-5 operands
    float w3r = (t < H2) ? W3[t] : 0.0f;
    float b3r = (t == 0) ? b3[0] : 0.0f;

    // Tiny shared vectors
    if (t < IN)   sm[OFF_X + t]  = x[t];
    if (t < FEAT) sm[OFF_H0 + t] = h0[t];
    __syncthreads();

    // ================= Stage 1: gates (thread t = gate row t) ================
    {
        const float* wi = sm + OFF_WIH + t * PITCH_IH;   // stride 9: CF
        const float* wh = sm + OFF_WHH + t * PITCH_HH;   // stride 11: CF
        const float* xx = sm + OFF_X;
        const float* hr = sm + OFF_H0 + (t / 40) * HID;
        float acc = bias;
        #pragma unroll
        for (int i = 0; i < IN; ++i)  acc = fmaf(wi[i], xx[i], acc);
        #pragma unroll
        for (int j = 0; j < HID; ++j) acc = fmaf(wh[j], hr[j], acc);
        sm[OFF_GATES + t] = acc;
    }
    __syncthreads();

    // ================= Stage 2: LSTM pointwise + feature reorder ==============
    if (t < FEAT) {
        const int cell = t / HID;
        const float* g = sm + OFF_GATES + cell * 40 + (t % HID);
        float ig = sigmoid_fast(g[0]);
        float fg = sigmoid_fast(g[10]);
        float gg = tanh_fast(g[20]);
        float og = sigmoid_fast(g[30]);
        float c = fmaf(fg, c0r, ig * gg);
        float h = og * tanh_fast(c);
        int fidx = (cell >= 10) ? (t - 100) : (100 + t);   // gen bank first
        sm[OFF_FEAT + fidx] = h;
    }
    __syncthreads();

    // ================= Stage 3: h1 = tanh(W1 @ feat + b1), 16 lanes/row ======
    {
        const float* f = sm + OFF_FEAT;
        float sum = 0.0f;
        #pragma unroll
        for (int u = 0; u < 12; ++u)
            sum = fmaf(w1r[u], f[lane16 + (u << 4)], sum);
        if (lane16 < 8)
            sum = fmaf(w1t, f[192 + lane16], sum);
        sum += __shfl_xor_sync(0xffffffffu, sum, 8);
        sum += __shfl_xor_sync(0xffffffffu, sum, 4);
        sum += __shfl_xor_sync(0xffffffffu, sum, 2);
        sum += __shfl_xor_sync(0xffffffffu, sum, 1);
        if (lane16 == 0) sm[OFF_H1 + row16] = tanh_fast(sum + b1r);
    }
    __syncthreads();

    // ================= Stage 4: h2 = tanh(W2 @ h1 + b2), 1 warp/row ==========
    if (t < H2 * 32) {
        const int l4 = t & 31;
        float sum = w2a * sm[OFF_H1 + l4];
        if (l4 < H1 - 32) sum = fmaf(w2b, sm[OFF_H1 + 32 + l4], sum);
        #pragma unroll
        for (int m = 16; m > 0; m >>= 1)
            sum += __shfl_xor_sync(0xffffffffu, sum, m);
        if (l4 == 0) sm[OFF_H2 + (t >> 5)] = tanh_fast(sum + b2r);
    }
    __syncthreads();

    // ================= Stage 5: out = tanh(W3 @ h2 + b3), 1 warp =============
    if (t < 32) {
        float sum = (t < H2) ? w3r * sm[OFF_H2 + t] : 0.0f;
        #pragma unroll
        for (int m = 16; m > 0; m >>= 1)
            sum += __shfl_xor_sync(0xffffffffu, sum, m);
        if (t == 0) out[0] = tanh_fast(sum + b3r);
    }
}

extern "C" void kernel_launch(void* const* d_in, const int* in_sizes, int n_in,
                              void* d_out, int out_size) {
    (void)in_sizes; (void)n_in; (void)out_size;
    const float* x    = (const float*)d_in[0];
    const float* h0   = (const float*)d_in[1];
    const float* c0   = (const float*)d_in[2];
    const float* W_ih = (const float*)d_in[3];
    const float* W_hh = (const float*)d_in[4];
    const float* b_ih = (const float*)d_in[5];
    const float* b_hh = (const float*)d_in[6];
    const float* W1   = (const float*)d_in[7];
    const float* b1   = (const float*)d_in[8];
    const float* W2   = (const float*)d_in[9];
    const float* b2   = (const float*)d_in[10];
    const float* W3   = (const float*)d_in[11];
    const float* b3   = (const float*)d_in[12];
    float* out = (float*)d_out;

    static bool attr_set = false;
    if (!attr_set) {
        cudaFuncSetAttribute(lstm_mlp_fused,
                             cudaFuncAttributeMaxDynamicSharedMemorySize,
                             SMEM_BYTES);
        attr_set = true;
    }

    lstm_mlp_fused<<<1, 800, SMEM_BYTES>>>(x, h0, c0, W_ih, W_hh, b_ih, b_hh,
                                           W1, b1, W2, b2, W3, b3, out);
}